// round 10
// baseline (speedup 1.0000x reference)
#include <cuda_runtime.h>

// HSTU positional encoder — register-MLP R=8 champion + register-level
// dedup of redundant ts/pos table gathers (runs of equal indices).
// out[i,:] = x[i,:]*sqrt(D) + pos_weight[pos_ind(i),:] + ts_weight[ts_ind(i),:]
// D = 512 fp32, L = 32768, B = 16, P = 8192, NTB = 2048.

#define D 512
#define ALPHA 22.627416997969522f   // sqrt(512)
#define MAX_POS 8192
#define NTB 2048
#define TIME_BUCKET_INCREMENTS 60.0f
#define R 8                          // rows per CTA

__global__ __launch_bounds__(128)
void hstu_pos_enc_dedup(
    const int* __restrict__ seq_lengths,   // [B]
    const int* __restrict__ seq_offsets,   // [B+1]
    const float* __restrict__ x,           // [L, D]
    const int* __restrict__ num_targets,   // [B]
    const int* __restrict__ seq_ts,        // [L]
    const float* __restrict__ pos_weight,  // [P, D]
    const float* __restrict__ ts_weight,   // [NTB+1, D]
    float* __restrict__ out,               // [L, D]
    int B, int L)
{
    const int base = blockIdx.x * R;
    const int lane = threadIdx.x & 31;

    // Lanes 0..R-1 each compute the index pair for row base+lane.
    int pos_i = 0, ts_i = 0;
    if (lane < R && base + lane < L) {
        const int row = base + lane;

        int lo = 0, hi = B - 1;
        while (lo < hi) {
            int mid = (lo + hi + 1) >> 1;
            if (seq_offsets[mid] <= row) lo = mid; else hi = mid - 1;
        }
        const int b = lo;

        const int off = seq_offsets[b];
        const int rel_pos = row - off;

        int len = seq_lengths[b]; if (len < 0) len = 0;
        int nt  = num_targets[b]; if (nt  < 0) nt  = 0;
        int high_ind = len - nt;  if (high_ind < 0) high_ind = 0;

        int p = (rel_pos < high_ind) ? rel_pos : high_ind;
        p = high_ind - p;                   // MAX_CONTEXTUAL_SEQ_LEN = 0
        if (p > MAX_POS - 1) p = MAX_POS - 1;
        if (p < 0) p = 0;
        pos_i = p;

        const int end = seq_offsets[b + 1];
        const float qt = (float)seq_ts[end - 1];
        const float tt = (float)seq_ts[row];
        float dt = qt - tt;                 // TIME_DELTA = 0
        if (dt < 1e-6f) dt = 1e-6f;
        dt = dt / TIME_BUCKET_INCREMENTS;
        const float v = sqrtf(dt);          // TIME_BUCKET_SCALE = 1
        int ti = (int)v;
        if (ti > NTB) ti = NTB;
        ts_i = ti;
    }

    const int t = threadIdx.x;

    // Broadcast indices; mark each row unique iff its index differs from the
    // previous row's (runs of equal indices collapse to one load).
    int pos_ind[R], ts_ind[R];
    #pragma unroll
    for (int r = 0; r < R; r++) {
        pos_ind[r] = __shfl_sync(0xFFFFFFFFu, pos_i, r);
        ts_ind[r]  = __shfl_sync(0xFFFFFFFFu, ts_i,  r);
    }

    const float4* xp[R];
    #pragma unroll
    for (int r = 0; r < R; r++)
        xp[r] = (const float4*)(x + (size_t)(base + r) * D) + t;

    // Issue x loads first (always needed, stream-once).
    float4 xv[R];
    #pragma unroll
    for (int r = 0; r < R; r++) xv[r] = __ldcs(xp[r]);

    // Table loads with run-dedup: predicated LDG only where index changes.
    float4 pv[R], tv[R];
    #pragma unroll
    for (int r = 0; r < R; r++) {
        if (r == 0 || pos_ind[r] != pos_ind[r - 1])
            pv[r] = __ldg((const float4*)(pos_weight + (size_t)pos_ind[r] * D) + t);
    }
    #pragma unroll
    for (int r = 0; r < R; r++) {
        if (r == 0 || ts_ind[r] != ts_ind[r - 1])
            tv[r] = __ldg((const float4*)(ts_weight + (size_t)ts_ind[r] * D) + t);
    }
    // Propagate registers along runs.
    #pragma unroll
    for (int r = 1; r < R; r++) {
        if (pos_ind[r] == pos_ind[r - 1]) pv[r] = pv[r - 1];
        if (ts_ind[r]  == ts_ind[r - 1])  tv[r] = tv[r - 1];
    }

    #pragma unroll
    for (int r = 0; r < R; r++) {
        const int row = base + r;
        if (row < L) {
            float4 ov;
            ov.x = fmaf(xv[r].x, ALPHA, pv[r].x + tv[r].x);
            ov.y = fmaf(xv[r].y, ALPHA, pv[r].y + tv[r].y);
            ov.z = fmaf(xv[r].z, ALPHA, pv[r].z + tv[r].z);
            ov.w = fmaf(xv[r].w, ALPHA, pv[r].w + tv[r].w);
            __stcs((float4*)(out + (size_t)row * D) + t, ov);   // stream-once
        }
    }
}

extern "C" void kernel_launch(void* const* d_in, const int* in_sizes, int n_in,
                              void* d_out, int out_size)
{
    // Input order (metadata): [max_seq_len?], seq_lengths, seq_offsets,
    // seq_embeddings, num_targets, seq_timestamps, pos_weight, ts_weight.
    int o = (n_in == 8) ? 1 : 0;

    const int*   seq_lengths = (const int*)  d_in[o + 0];
    const int*   seq_offsets = (const int*)  d_in[o + 1];
    const float* x           = (const float*)d_in[o + 2];
    const int*   num_targets = (const int*)  d_in[o + 3];
    const int*   seq_ts      = (const int*)  d_in[o + 4];
    const float* pos_weight  = (const float*)d_in[o + 5];
    const float* ts_weight   = (const float*)d_in[o + 6];
    float*       out         = (float*)d_out;

    const int B = in_sizes[o + 0];          // seq_lengths element count
    const int L = out_size / D;             // total token rows

    const int grid = (L + R - 1) / R;
    hstu_pos_enc_dedup<<<grid, 128>>>(seq_lengths, seq_offsets, x, num_targets,
                                      seq_ts, pos_weight, ts_weight, out, B, L);
}

// round 11
// speedup vs baseline: 1.2914x; 1.2914x over previous
#include <cuda_runtime.h>

// HSTU positional encoder — R=8 register-MLP champion + O(1)-register ts dedup.
// out[i,:] = x[i,:]*sqrt(D) + pos_weight[pos_ind(i),:] + ts_weight[ts_ind(i),:]
// D = 512 fp32, L = 32768, B = 16, P = 8192, NTB = 2048.
// ts_ind is monotone (non-increasing) within consecutive rows of a batch, with
// long runs -> a CTA almost always sees 1 or 2 distinct ts rows.

#define D 512
#define ALPHA 22.627416997969522f   // sqrt(512)
#define MAX_POS 8192
#define NTB 2048
#define TIME_BUCKET_INCREMENTS 60.0f
#define R 8                          // rows per CTA

__global__ __launch_bounds__(128)
void hstu_pos_enc_tsd(
    const int* __restrict__ seq_lengths,   // [B]
    const int* __restrict__ seq_offsets,   // [B+1]
    const float* __restrict__ x,           // [L, D]
    const int* __restrict__ num_targets,   // [B]
    const int* __restrict__ seq_ts,        // [L]
    const float* __restrict__ pos_weight,  // [P, D]
    const float* __restrict__ ts_weight,   // [NTB+1, D]
    float* __restrict__ out,               // [L, D]
    int B, int L)
{
    const int base = blockIdx.x * R;
    const int lane = threadIdx.x & 31;

    // Lanes 0..R-1 each compute the index pair for row base+lane.
    int pos_i = 0, ts_i = 0;
    if (lane < R && base + lane < L) {
        const int row = base + lane;

        int lo = 0, hi = B - 1;
        while (lo < hi) {
            int mid = (lo + hi + 1) >> 1;
            if (seq_offsets[mid] <= row) lo = mid; else hi = mid - 1;
        }
        const int b = lo;

        const int off = seq_offsets[b];
        const int rel_pos = row - off;

        int len = seq_lengths[b]; if (len < 0) len = 0;
        int nt  = num_targets[b]; if (nt  < 0) nt  = 0;
        int high_ind = len - nt;  if (high_ind < 0) high_ind = 0;

        int p = (rel_pos < high_ind) ? rel_pos : high_ind;
        p = high_ind - p;                   // MAX_CONTEXTUAL_SEQ_LEN = 0
        if (p > MAX_POS - 1) p = MAX_POS - 1;
        if (p < 0) p = 0;
        pos_i = p;

        const int end = seq_offsets[b + 1];
        const float qt = (float)seq_ts[end - 1];
        const float tt = (float)seq_ts[row];
        float dt = qt - tt;                 // TIME_DELTA = 0
        if (dt < 1e-6f) dt = 1e-6f;
        dt = dt / TIME_BUCKET_INCREMENTS;
        const float v = sqrtf(dt);          // TIME_BUCKET_SCALE = 1
        int ti = (int)v;
        if (ti > NTB) ti = NTB;
        ts_i = ti;
    }

    const int t = threadIdx.x;

    int pos_ind[R], ts_ind[R];
    #pragma unroll
    for (int r = 0; r < R; r++) {
        pos_ind[r] = __shfl_sync(0xFFFFFFFFu, pos_i, r);
        ts_ind[r]  = __shfl_sync(0xFFFFFFFFu, ts_i,  r);
    }

    // Batched x + pos loads (16 independent LDG.128), as in the champion.
    float4 xv[R], pv[R];
    #pragma unroll
    for (int r = 0; r < R; r++)
        xv[r] = __ldcs((const float4*)(x + (size_t)(base + r) * D) + t);
    #pragma unroll
    for (int r = 0; r < R; r++)
        pv[r] = __ldg((const float4*)(pos_weight + (size_t)pos_ind[r] * D) + t);

    // ts dedup: at most two table rows cover the CTA in the common case.
    const int ts0 = ts_ind[0];
    const int ts7 = ts_ind[R - 1];
    float4 tv_head = __ldg((const float4*)(ts_weight + (size_t)ts0 * D) + t);
    float4 tv_tail = tv_head;
    if (ts7 != ts0)   // warp-uniform branch
        tv_tail = __ldg((const float4*)(ts_weight + (size_t)ts7 * D) + t);

    #pragma unroll
    for (int r = 0; r < R; r++) {
        const int row = base + r;
        if (row < L) {
            float4 tv;
            if (ts_ind[r] == ts0)       tv = tv_head;
            else if (ts_ind[r] == ts7)  tv = tv_tail;
            else  // rare short-run CTA: per-row fallback
                tv = __ldg((const float4*)(ts_weight + (size_t)ts_ind[r] * D) + t);

            float4 ov;
            ov.x = fmaf(xv[r].x, ALPHA, pv[r].x + tv.x);
            ov.y = fmaf(xv[r].y, ALPHA, pv[r].y + tv.y);
            ov.z = fmaf(xv[r].z, ALPHA, pv[r].z + tv.z);
            ov.w = fmaf(xv[r].w, ALPHA, pv[r].w + tv.w);
            __stcs((float4*)(out + (size_t)row * D) + t, ov);   // stream-once
        }
    }
}

extern "C" void kernel_launch(void* const* d_in, const int* in_sizes, int n_in,
                              void* d_out, int out_size)
{
    // Input order (metadata): [max_seq_len?], seq_lengths, seq_offsets,
    // seq_embeddings, num_targets, seq_timestamps, pos_weight, ts_weight.
    int o = (n_in == 8) ? 1 : 0;

    const int*   seq_lengths = (const int*)  d_in[o + 0];
    const int*   seq_offsets = (const int*)  d_in[o + 1];
    const float* x           = (const float*)d_in[o + 2];
    const int*   num_targets = (const int*)  d_in[o + 3];
    const int*   seq_ts      = (const int*)  d_in[o + 4];
    const float* pos_weight  = (const float*)d_in[o + 5];
    const float* ts_weight   = (const float*)d_in[o + 6];
    float*       out         = (float*)d_out;

    const int B = in_sizes[o + 0];          // seq_lengths element count
    const int L = out_size / D;             // total token rows

    const int grid = (L + R - 1) / R;
    hstu_pos_enc_tsd<<<grid, 128>>>(seq_lengths, seq_offsets, x, num_targets,
                                    seq_ts, pos_weight, ts_weight, out, B, L);
}